// round 5
// baseline (speedup 1.0000x reference)
#include <cuda_runtime.h>

constexpr int kB = 32;
constexpr int kA = 5;
constexpr int kC = 8;
constexpr int kH = 32;
constexpr int kW = 64;
constexpr int kT = 50;
constexpr int kCh = 7 + kC;                 // 15
constexpr int kHW = kH * kW;                // 2048
constexpr int kCellsPerB = kA * kHW;        // 10240
constexpr int kG = 8;                       // row groups of 4 rows
constexpr int kBlocksPerB = 40;             // 5 anchors * 8 rowgroups
constexpr int kGrid = kB * kBlocksPerB;     // 1280

__constant__ float c_aw[kA] = {1.08f, 3.42f, 6.63f, 9.42f, 16.62f};
__constant__ float c_al[kA] = {1.19f, 4.41f, 11.38f, 5.11f, 10.52f};

// ---------------- global scratch (L2-resident) ------------------------------
__device__ int    g_nc[kB][kG];
__device__ float4 g_cbox[kB][kG][kT];     // culled boxes: x1, 1.6*y1, x2, 1.6*y2
__device__ float  g_cna[kB][kG][kT];      // -0.6 * target area
__device__ int    g_nm[kB];
__device__ int    g_mlin[kB][kT];         // matched cell lin (within batch)
__device__ float  g_mdata[kB][kT][12];    // tx,ty,tw,tl,tim,tre,tcls, bx1,by1s,bx2,by2s
__device__ float        g_partials[kGrid];
__device__ unsigned int g_count = 0;      // self-resets -> graph-replay deterministic

// ---------------------------------------------------------------------------
// Prep kernel: 1 block per batch, 64 threads. All the expensive per-target
// work happens exactly once per batch.
// ---------------------------------------------------------------------------
__global__ void __launch_bounds__(64) k_prep(const float* __restrict__ tgt) {
    const int b = blockIdx.x;
    const int t = threadIdx.x;

    __shared__ int      s_lin[kT];
    __shared__ unsigned s_mask[2];
    __shared__ int      s_cnt[kG];
    __shared__ int      s_nm;

    if (t < kG) s_cnt[t] = 0;
    if (t == 0) s_nm = 0;

    float gx = 0.f, gy = 0.f, gw = 0.f, gl = 0.f, garea = 0.f;
    float t0 = 0.f, t5 = 0.f, t6 = 0.f;
    int gi = 0, gj = 0, besta = 0;
    float4 box = make_float4(0.f, 0.f, 0.f, 0.f);
    bool validt = false;

    if (t < kT) {
        const float* tr = tgt + ((size_t)b * kT + t) * 7;
        t0 = tr[0];
        float t1 = tr[1], t2 = tr[2], t3 = tr[3], t4 = tr[4];
        t5 = tr[5]; t6 = tr[6];
        validt = (t1 != 0.0f);

        gx = t1 * (float)kW;
        gy = t2 * (float)kH;
        gw = t3 * (float)kW;
        gl = t4 * (float)kH;
        gi = min(max((int)gx, 0), kW - 1);
        gj = min(max((int)gy, 0), kH - 1);
        garea = gw * gl;

        float bestv = -1e30f;
#pragma unroll
        for (int q = 0; q < kA; q++) {
            float inter = fminf(gw, c_aw[q]) * fminf(gl, c_al[q]);
            float uni = garea + c_aw[q] * c_al[q] - inter;
            float v = inter / uni;
            if (v > bestv) { bestv = v; besta = q; }
        }
        s_lin[t] = (besta * kH + gj) * kW + gi;
        box = make_float4(gx - gw * 0.5f, 1.6f * (gy - gl * 0.5f),
                          gx + gw * 0.5f, 1.6f * (gy + gl * 0.5f));
    }
    unsigned bm = __ballot_sync(0xffffffffu, validt);
    if ((t & 31) == 0) s_mask[t >> 5] = bm;
    __syncthreads();

    unsigned long long mm = (unsigned long long)s_mask[0]
                          | ((unsigned long long)s_mask[1] << 32);
    const int nv = __ffsll((long long)~mm) - 1;   // cumprod validity prefix

    if (t < nv) {
        // segment_max dedupe: last valid target per cell wins
        int mylin = s_lin[t];
        bool kept = true;
        for (int u = t + 1; u < nv; u++)
            if (s_lin[u] == mylin) { kept = false; break; }
        if (kept) {
            int p = atomicAdd(&s_nm, 1);
            g_mlin[b][p] = mylin;
            float* md = g_mdata[b][p];
            md[0] = gx - (float)gi;
            md[1] = gy - (float)gj;
            md[2] = logf(gw / c_aw[besta]);
            md[3] = logf(gl / c_al[besta]);
            md[4] = t5;
            md[5] = t6;
            md[6] = t0;
            md[7] = box.x; md[8] = box.y; md[9] = box.z; md[10] = box.w;
            md[11] = 0.f;
        }
        // y-distance culling per rowgroup: IoU>0.6 requires |py-ty| < tl/3
        float tl3 = gl * (1.0f / 3.0f) + 1e-3f;
        float na = -0.6f * garea;
#pragma unroll
        for (int g = 0; g < kG; g++) {
            float jlo = (float)(4 * g);
            if (gy + tl3 > jlo && gy - tl3 < jlo + 4.0f) {
                int p = atomicAdd(&s_cnt[g], 1);
                g_cbox[b][g][p] = box;
                g_cna[b][g][p]  = na;
            }
        }
    }
    __syncthreads();
    if (t < kG) g_nc[b][t] = s_cnt[t];
    if (t == 0) g_nm[b] = s_nm;
}

// ---------------------------------------------------------------------------
// Main kernel: 1 thread per cell. Block = one anchor x 4 rows x 64 cols.
// ---------------------------------------------------------------------------
__global__ void __launch_bounds__(256) k_main(const float* __restrict__ out,
                                              float* __restrict__ loss,
                                              int out_size) {
    __shared__ float4 cbox[kT];
    __shared__ float  cna[kT];
    __shared__ short  s_map[256];
    __shared__ float  red[256];
    __shared__ bool   s_last;

    const int tid = threadIdx.x;
    const int bid = blockIdx.x;
    const int b   = bid / kBlocksPerB;
    const int cb  = bid - b * kBlocksPerB;
    const int a   = cb >> 3;
    const int g   = cb & 7;
    const int cellbase = cb * 256;
    const int rem = (cellbase + tid) & 2047;
    const int i   = rem & 63;
    const int j   = rem >> 6;

    // channel LDGs up front (latency overlapped with smem staging)
    const float* base = out + ((size_t)(b * kA + a) * kCh) * kHW + rem;
    float c0 = base[0 * kHW];
    float c1 = base[1 * kHW];
    float c2 = base[2 * kHW];
    float c3 = base[3 * kHW];
    float c4 = base[4 * kHW];
    float c5 = base[5 * kHW];
    float c6 = base[6 * kHW];

    const int nc = g_nc[b][g];
    const int nm = g_nm[b];

    s_map[tid] = -1;
    if (tid < nc) {
        cbox[tid] = g_cbox[b][g][tid];
        cna[tid]  = g_cna[b][g][tid];
    }
    __syncthreads();
    if (tid < nm) {
        int off = g_mlin[b][tid] - cellbase;
        if (off >= 0 && off < 256) s_map[off] = (short)tid;
    }
    __syncthreads();

    // per-cell derived values
    float sxv  = 1.0f / (1.0f + __expf(-c0));
    float syv  = 1.0f / (1.0f + __expf(-c1));
    float conf = 1.0f / (1.0f + __expf(-c6));

    float pw = __expf(c2) * c_aw[a];
    float pl = __expf(c3) * c_al[a];
    float px = sxv + (float)i;
    float py = syv + (float)j;

    float x1 = px - pw * 0.5f, x2 = px + pw * 0.5f;
    float y1s = 1.6f * (py - pl * 0.5f), y2s = 1.6f * (py + pl * 0.5f);
    float parea = pw * pl;
    float th = 0.6f * parea;

    // exists(iou > 0.6) over culled targets (dual accumulators for ILP)
    float bA = -1e30f, bB = -1e30f;
    int t = 0;
    for (; t + 2 <= nc; t += 2) {
        float4 q0 = cbox[t];
        float  n0 = cna[t];
        float4 q1 = cbox[t + 1];
        float  n1 = cna[t + 1];
        float cw0 = fminf(x2, q0.z) - fmaxf(x1, q0.x);
        float ch0 = fminf(y2s, q0.w) - fmaxf(y1s, q0.y);
        bA = fmaxf(bA, fmaf(fmaxf(cw0, 0.0f), ch0, n0));
        float cw1 = fminf(x2, q1.z) - fmaxf(x1, q1.x);
        float ch1 = fminf(y2s, q1.w) - fmaxf(y1s, q1.y);
        bB = fmaxf(bB, fmaf(fmaxf(cw1, 0.0f), ch1, n1));
    }
    if (t < nc) {
        float4 q0 = cbox[t];
        float  n0 = cna[t];
        float cw0 = fminf(x2, q0.z) - fmaxf(x1, q0.x);
        float ch0 = fminf(y2s, q0.w) - fmaxf(y1s, q0.y);
        bA = fmaxf(bA, fmaf(fmaxf(cw0, 0.0f), ch0, n0));
    }
    bool found = fmaxf(bA, bB) > th;

    const int map = s_map[tid];
    float acc;
    if (map >= 0) {
        const float* md = g_mdata[b][map];
        float dx   = sxv - md[0];
        float dy   = syv - md[1];
        float dw   = c2  - md[2];
        float dl   = c3  - md[3];
        float dim_ = c4  - md[4];
        float dre  = c5  - md[5];

        float bx1 = md[7], by1s = md[8], bx2 = md[9], by2s = md[10];
        float cw  = fminf(x2, bx2) - fmaxf(x1, bx1);
        float chs = fminf(y2s, by2s) - fmaxf(y1s, by1s);
        float inter = fmaxf(cw, 0.0f) * fmaxf(chs, 0.0f) * 0.625f;
        float tgw = bx2 - bx1;
        float tgl = (by2s - by1s) * 0.625f;
        float uni = parea + tgw * tgl - inter;
        float tconf = inter / uni;
        float dconf = conf * 10.0f - tconf * 10.0f;

        // lazy class-logit loads (matched cells only)
        float cl[kC];
#pragma unroll
        for (int q = 0; q < kC; q++) cl[q] = base[(size_t)(7 + q) * kHW];
        float mx = cl[0];
#pragma unroll
        for (int q = 1; q < kC; q++) mx = fmaxf(mx, cl[q]);
        float s = 0.0f;
#pragma unroll
        for (int q = 0; q < kC; q++) s += __expf(cl[q] - mx);
        int tcls = (int)md[6];
        float ce = mx + logf(s) - cl[tcls];

        acc = dx * dx + dy * dy + dw * dw + dl * dl + dim_ * dim_ + dre * dre
            + dconf * dconf + ce;
    } else {
        float cc = found ? 0.0f : conf;
        acc = cc * cc;
    }

    // reduction: block -> partials -> last block finishes (deterministic)
    red[tid] = acc;
    __syncthreads();
#pragma unroll
    for (int s2 = 128; s2 > 0; s2 >>= 1) {
        if (tid < s2) red[tid] += red[tid + s2];
        __syncthreads();
    }

    if (tid == 0) {
        g_partials[bid] = red[0];
        __threadfence();
        unsigned int r = atomicAdd(&g_count, 1u);
        s_last = (r == (unsigned)(kGrid - 1));
    }
    __syncthreads();

    if (s_last) {
        float s = 0.0f;
        for (int p = tid; p < kGrid; p += 256) s += __ldcg(&g_partials[p]);
        red[tid] = s;
        __syncthreads();
#pragma unroll
        for (int s2 = 128; s2 > 0; s2 >>= 1) {
            if (tid < s2) red[tid] += red[tid + s2];
            __syncthreads();
        }
        if (tid == 0) {
            loss[0] = red[0];
            g_count = 0;
        }
        for (int p = 1 + tid; p < out_size; p += 256) loss[p] = 0.0f;
    }
}

extern "C" void kernel_launch(void* const* d_in, const int* in_sizes, int n_in,
                              void* d_out, int out_size) {
    const float* output = (const float*)d_in[0];
    const float* target = (const float*)d_in[1];
    k_prep<<<kB, 64>>>(target);
    k_main<<<kGrid, 256>>>(output, (float*)d_out, out_size);
}

// round 6
// speedup vs baseline: 1.1807x; 1.1807x over previous
#include <cuda_runtime.h>

constexpr int kB = 32;
constexpr int kA = 5;
constexpr int kC = 8;
constexpr int kH = 32;
constexpr int kW = 64;
constexpr int kT = 50;
constexpr int kCh = 7 + kC;                 // 15
constexpr int kHW = kH * kW;                // 2048
constexpr int kBlocksPerB = 40;             // 5 anchors * 8 rowgroups(4 rows)
constexpr int kGrid = kB * kBlocksPerB;     // 1280

__constant__ float c_aw[kA] = {1.08f, 3.42f, 6.63f, 9.42f, 16.62f};
__constant__ float c_al[kA] = {1.19f, 4.41f, 11.38f, 5.11f, 10.52f};

__device__ float        g_partials[kGrid];
__device__ unsigned int g_count = 0;   // self-resets -> graph-replay deterministic

// ---------------------------------------------------------------------------
// Rare path (<=50 threads per batch): full matched-cell loss, recomputed from
// the raw target row. Kept out of line so the hot path stays at ~32 regs.
// ---------------------------------------------------------------------------
__device__ __noinline__ float matched_loss(
    const float* __restrict__ tr, const float* __restrict__ base,
    float sxv, float syv, float conf,
    float c2, float c3, float c4, float c5,
    float x1, float x2, float y1s, float y2s, float parea)
{
    float t0 = tr[0], t1 = tr[1], t2 = tr[2], t3 = tr[3];
    float t4 = tr[4], t5 = tr[5], t6 = tr[6];
    float gx = t1 * (float)kW;
    float gy = t2 * (float)kH;
    float gw = t3 * (float)kW;
    float gl = t4 * (float)kH;
    int gi = min(max((int)gx, 0), kW - 1);
    int gj = min(max((int)gy, 0), kH - 1);
    float garea = gw * gl;

    // division-free first-max-wins anchor argmax (same formula as prep)
    int besta = 0;
    float bin = fminf(gw, c_aw[0]) * fminf(gl, c_al[0]);
    float bun = garea + c_aw[0] * c_al[0] - bin;
#pragma unroll
    for (int q = 1; q < kA; q++) {
        float in_ = fminf(gw, c_aw[q]) * fminf(gl, c_al[q]);
        float un_ = garea + c_aw[q] * c_al[q] - in_;
        if (in_ * bun > bin * un_) { besta = q; bin = in_; bun = un_; }
    }

    float dx   = sxv - (gx - (float)gi);
    float dy   = syv - (gy - (float)gj);
    float dw   = c2 - logf(gw / c_aw[besta]);
    float dl   = c3 - logf(gl / c_al[besta]);
    float dim_ = c4 - t5;
    float dre  = c5 - t6;

    float bx1 = gx - gw * 0.5f, bx2 = gx + gw * 0.5f;
    float by1s = 1.6f * (gy - gl * 0.5f), by2s = 1.6f * (gy + gl * 0.5f);
    float cw  = fminf(x2, bx2) - fmaxf(x1, bx1);
    float chs = fminf(y2s, by2s) - fmaxf(y1s, by1s);
    float inter = fmaxf(cw, 0.0f) * fmaxf(chs, 0.0f) * 0.625f;
    float uni = parea + garea - inter;
    float tconf = inter / uni;
    float dconf = conf * 10.0f - tconf * 10.0f;

    float cl[kC];
#pragma unroll
    for (int q = 0; q < kC; q++) cl[q] = base[(size_t)(7 + q) * kHW];
    float mx = cl[0];
#pragma unroll
    for (int q = 1; q < kC; q++) mx = fmaxf(mx, cl[q]);
    float s = 0.0f;
#pragma unroll
    for (int q = 0; q < kC; q++) s += __expf(cl[q] - mx);
    int tcls = (int)t0;
    float ce = mx + logf(s) - cl[tcls];

    return dx * dx + dy * dy + dw * dw + dl * dl + dim_ * dim_ + dre * dre
         + dconf * dconf + ce;
}

__global__ void __launch_bounds__(256) k_fused(const float* __restrict__ out,
                                               const float* __restrict__ tgt,
                                               float* __restrict__ loss,
                                               int out_size) {
    __shared__ float4   cbox[kT];
    __shared__ float    cna[kT];
    __shared__ int      s_lin[kT];
    __shared__ unsigned s_mask[2];
    __shared__ short    s_map[256];
    __shared__ int      s_cnt;
    __shared__ float    red[256];
    __shared__ bool     s_last;

    const int tid = threadIdx.x;
    const int bid = blockIdx.x;
    const int b   = bid / kBlocksPerB;
    const int cb  = bid - b * kBlocksPerB;
    const int a   = cb >> 3;
    const int g   = cb & 7;
    const int cellbase = cb * 256;
    const int rem = (cellbase + tid) & 2047;
    const int i   = rem & 63;
    const int j   = rem >> 6;

    // channel LDGs first — latency overlaps the whole prep phase
    const float* base = out + ((size_t)(b * kA + a) * kCh) * kHW + rem;
    float c0 = base[0 * kHW];
    float c1 = base[1 * kHW];
    float c2 = base[2 * kHW];
    float c3 = base[3 * kHW];
    float c4 = base[4 * kHW];
    float c5 = base[5 * kHW];
    float c6 = base[6 * kHW];

    // ---------------- cheap per-block prep ----------------------------------
    s_map[tid] = -1;
    if (tid == 0) s_cnt = 0;

    const float* tr = tgt + ((size_t)b * kT + tid) * 7;
    bool validt = false;
    float gy = 0.f, gl = 0.f;
    float4 box = make_float4(0.f, 0.f, 0.f, 0.f);
    float na = 0.f;
    int lin = -1;

    if (tid < kT) validt = (tr[1] != 0.0f);
    unsigned bm = __ballot_sync(0xffffffffu, validt);
    if ((tid & 31) == 0 && tid < 64) s_mask[tid >> 5] = bm;

    if (validt) {
        float t1 = tr[1], t2 = tr[2], t3 = tr[3], t4 = tr[4];
        float gx = t1 * (float)kW;
        gy = t2 * (float)kH;
        float gw = t3 * (float)kW;
        gl = t4 * (float)kH;
        int gi = min(max((int)gx, 0), kW - 1);
        int gj = min(max((int)gy, 0), kH - 1);
        float garea = gw * gl;

        // division-free first-max-wins argmax
        int besta = 0;
        float bin = fminf(gw, c_aw[0]) * fminf(gl, c_al[0]);
        float bun = garea + c_aw[0] * c_al[0] - bin;
#pragma unroll
        for (int q = 1; q < kA; q++) {
            float in_ = fminf(gw, c_aw[q]) * fminf(gl, c_al[q]);
            float un_ = garea + c_aw[q] * c_al[q] - in_;
            if (in_ * bun > bin * un_) { besta = q; bin = in_; bun = un_; }
        }
        lin = (besta * kH + gj) * kW + gi;
        box = make_float4(gx - gw * 0.5f, 1.6f * (gy - gl * 0.5f),
                          gx + gw * 0.5f, 1.6f * (gy + gl * 0.5f));
        na = -0.6f * garea;
    }
    if (tid < kT) s_lin[tid] = validt ? lin : -1;
    __syncthreads();

    unsigned long long mm = (unsigned long long)s_mask[0]
                          | ((unsigned long long)s_mask[1] << 32);
    const int nv = __ffsll((long long)~mm) - 1;   // cumprod-validity prefix length

    if (tid < nv) {
        // segment_max dedupe: last valid target with this lin wins
        bool kept = true;
        for (int u = tid + 1; u < nv; u++)
            if (s_lin[u] == lin) { kept = false; break; }
        if (kept) {
            int off = lin - cellbase;
            if (off >= 0 && off < 256) s_map[off] = (short)tid;
        }
        // y-distance cull for this block's 4 rows: IoU>0.6 needs |py-ty| < tl/3
        float tl3 = gl * (1.0f / 3.0f) + 1e-3f;
        float jlo = (float)(4 * g);
        if (gy + tl3 > jlo && gy - tl3 < jlo + 4.0f) {
            int p = atomicAdd(&s_cnt, 1);
            cbox[p] = box;
            cna[p]  = na;
        }
    }
    __syncthreads();

    // ---------------- per-cell derived values -------------------------------
    float sxv  = 1.0f / (1.0f + __expf(-c0));
    float syv  = 1.0f / (1.0f + __expf(-c1));
    float conf = 1.0f / (1.0f + __expf(-c6));

    float pw = __expf(c2) * c_aw[a];
    float pl = __expf(c3) * c_al[a];
    float px = sxv + (float)i;
    float py = syv + (float)j;

    float x1 = px - pw * 0.5f, x2 = px + pw * 0.5f;
    float y1s = 1.6f * (py - pl * 0.5f), y2s = 1.6f * (py + pl * 0.5f);
    float parea = pw * pl;
    float th = 0.6f * parea;

    // ---------------- exists(iou > 0.6) over culled targets -----------------
    const int nc = s_cnt;
    float bA = -1e30f, bB = -1e30f;
    int t = 0;
    for (; t + 4 <= nc; t += 4) {
        float4 q0 = cbox[t];
        float4 q1 = cbox[t + 1];
        float4 q2 = cbox[t + 2];
        float4 q3 = cbox[t + 3];
        float n0 = cna[t], n1 = cna[t + 1], n2 = cna[t + 2], n3 = cna[t + 3];

        float cw0 = fminf(x2, q0.z) - fmaxf(x1, q0.x);
        float ch0 = fminf(y2s, q0.w) - fmaxf(y1s, q0.y);
        bA = fmaxf(bA, fmaf(fmaxf(cw0, 0.0f), ch0, n0));
        float cw1 = fminf(x2, q1.z) - fmaxf(x1, q1.x);
        float ch1 = fminf(y2s, q1.w) - fmaxf(y1s, q1.y);
        bB = fmaxf(bB, fmaf(fmaxf(cw1, 0.0f), ch1, n1));
        float cw2 = fminf(x2, q2.z) - fmaxf(x1, q2.x);
        float ch2 = fminf(y2s, q2.w) - fmaxf(y1s, q2.y);
        bA = fmaxf(bA, fmaf(fmaxf(cw2, 0.0f), ch2, n2));
        float cw3 = fminf(x2, q3.z) - fmaxf(x1, q3.x);
        float ch3 = fminf(y2s, q3.w) - fmaxf(y1s, q3.y);
        bB = fmaxf(bB, fmaf(fmaxf(cw3, 0.0f), ch3, n3));
    }
    for (; t < nc; t++) {
        float4 q0 = cbox[t];
        float  n0 = cna[t];
        float cw0 = fminf(x2, q0.z) - fmaxf(x1, q0.x);
        float ch0 = fminf(y2s, q0.w) - fmaxf(y1s, q0.y);
        bA = fmaxf(bA, fmaf(fmaxf(cw0, 0.0f), ch0, n0));
    }
    bool found = fmaxf(bA, bB) > th;

    const int map = s_map[tid];
    float acc;
    if (map >= 0) {
        acc = matched_loss(tgt + ((size_t)b * kT + map) * 7, base,
                           sxv, syv, conf, c2, c3, c4, c5,
                           x1, x2, y1s, y2s, parea);
    } else {
        float cc = found ? 0.0f : conf;
        acc = cc * cc;
    }

    // ---------------- reduction ---------------------------------------------
    red[tid] = acc;
    __syncthreads();
#pragma unroll
    for (int s2 = 128; s2 > 0; s2 >>= 1) {
        if (tid < s2) red[tid] += red[tid + s2];
        __syncthreads();
    }

    if (tid == 0) {
        g_partials[bid] = red[0];
        __threadfence();
        unsigned int r = atomicAdd(&g_count, 1u);
        s_last = (r == (unsigned)(kGrid - 1));
    }
    __syncthreads();

    if (s_last) {
        float s = 0.0f;
        for (int p = tid; p < kGrid; p += 256) s += __ldcg(&g_partials[p]);
        red[tid] = s;
        __syncthreads();
#pragma unroll
        for (int s2 = 128; s2 > 0; s2 >>= 1) {
            if (tid < s2) red[tid] += red[tid + s2];
            __syncthreads();
        }
        if (tid == 0) {
            loss[0] = red[0];
            g_count = 0;
        }
        for (int p = 1 + tid; p < out_size; p += 256) loss[p] = 0.0f;
    }
}

extern "C" void kernel_launch(void* const* d_in, const int* in_sizes, int n_in,
                              void* d_out, int out_size) {
    const float* output = (const float*)d_in[0];
    const float* target = (const float*)d_in[1];
    k_fused<<<kGrid, 256>>>(output, target, (float*)d_out, out_size);
}

// round 8
// speedup vs baseline: 1.6610x; 1.4068x over previous
#include <cuda_runtime.h>

constexpr int kB = 32;
constexpr int kA = 5;
constexpr int kC = 8;
constexpr int kH = 32;
constexpr int kW = 64;
constexpr int kT = 50;
constexpr int kCh = 7 + kC;                 // 15
constexpr int kHW = kH * kW;                // 2048
constexpr int kBlocksPerB = 40;             // 5 anchors * 8 rowgroups(4 rows)
constexpr int kGrid = kB * kBlocksPerB;     // 1280

__constant__ float c_aw[kA] = {1.08f, 3.42f, 6.63f, 9.42f, 16.62f};
__constant__ float c_al[kA] = {1.19f, 4.41f, 11.38f, 5.11f, 10.52f};

__device__ float        g_partials[kGrid];
__device__ unsigned int g_count = 0;   // self-resets -> graph-replay deterministic

__global__ void __launch_bounds__(256, 6) k_fused(const float* __restrict__ out,
                                                  const float* __restrict__ tgt,
                                                  float* __restrict__ loss,
                                                  int out_size) {
    // cbox: {x1, 1.6*y1, x2, 1.6*y2}  (min/max intersection form — exact)
    __shared__ float4   cbox[kT];
    __shared__ float    cna[kT];            // -0.6 * target area
    __shared__ float    std_[kT][12];       // tx,ty,tw,tl,tim,tre,tcls, x1,y1s,x2,y2s
    __shared__ int      s_map[256];
    __shared__ unsigned s_mask[2];
    __shared__ int      s_cnt;
    __shared__ float    wred[8];
    __shared__ bool     s_last;

    const int tid = threadIdx.x;
    const int bid = blockIdx.x;
    const int b   = bid / kBlocksPerB;
    const int cb  = bid - b * kBlocksPerB;
    const int a   = cb >> 3;
    const int g   = cb & 7;
    const int cellbase = cb * 256;
    const int rem = (cellbase + tid) & 2047;
    const int i   = rem & 63;
    const int j   = rem >> 6;

    // channel LDGs first — latency overlaps all of prep
    const float* base = out + ((size_t)(b * kA + a) * kCh) * kHW + rem;
    float c0 = base[0 * kHW];
    float c1 = base[1 * kHW];
    float c2 = base[2 * kHW];
    float c3 = base[3 * kHW];
    float c4 = base[4 * kHW];
    float c5 = base[5 * kHW];
    float c6 = base[6 * kHW];

    // ---------------- phase 1: per-target values + masks --------------------
    s_map[tid] = -1;
    if (tid == 0) s_cnt = 0;

    const float* tr = tgt + ((size_t)b * kT + tid) * 7;
    bool validt = (tid < kT) && (tr[1] != 0.0f);
    unsigned bm = __ballot_sync(0xffffffffu, validt);
    if ((tid & 31) == 0 && tid < 64) s_mask[tid >> 5] = bm;

    float gx = 0.f, gy = 0.f, gw = 0.f, gl = 0.f, garea = 0.f;
    int gi = 0, gj = 0, besta = 0, off = -1;
    if (validt) {
        gx = tr[1] * (float)kW;
        gy = tr[2] * (float)kH;
        gw = tr[3] * (float)kW;
        gl = tr[4] * (float)kH;
        gi = min(max((int)gx, 0), kW - 1);
        gj = min(max((int)gy, 0), kH - 1);
        garea = gw * gl;

        // division-free first-max-wins anchor argmax
        float bin = fminf(gw, c_aw[0]) * fminf(gl, c_al[0]);
        float bun = garea + c_aw[0] * c_al[0] - bin;
#pragma unroll
        for (int q = 1; q < kA; q++) {
            float in_ = fminf(gw, c_aw[q]) * fminf(gl, c_al[q]);
            float un_ = garea + c_aw[q] * c_al[q] - in_;
            if (in_ * bun > bin * un_) { besta = q; bin = in_; bun = un_; }
        }
        off = ((besta * kH + gj) * kW + gi) - cellbase;
    }
    __syncthreads();                                    // sync 1

    unsigned long long mm = (unsigned long long)s_mask[0]
                          | ((unsigned long long)s_mask[1] << 32);
    const int nv = __ffsll((long long)~mm) - 1;         // cumprod-validity prefix

    const bool inpfx = (tid < nv);
    if (inpfx) {
        // segment_max dedupe via atomicMax: max t (= last valid) wins
        if (off >= 0 && off < 256) atomicMax(&s_map[off], tid);
        // y-cull for this block's 4 rows: IoU>0.6 needs |py-ty| < tl/3
        float tl3 = gl * (1.0f / 3.0f) + 1e-3f;
        float jlo = (float)(4 * g);
        if (gy + tl3 > jlo && gy - tl3 < jlo + 4.0f) {
            int p = atomicAdd(&s_cnt, 1);
            cbox[p] = make_float4(gx - gw * 0.5f, 1.6f * (gy - gl * 0.5f),
                                  gx + gw * 0.5f, 1.6f * (gy + gl * 0.5f));
            cna[p]  = -0.6f * garea;
        }
    }
    __syncthreads();                                    // sync 2

    // phase 2: winners write regression targets (rare; hidden behind loop below)
    if (inpfx && off >= 0 && off < 256 && s_map[off] == tid) {
        std_[tid][0] = gx - (float)gi;
        std_[tid][1] = gy - (float)gj;
        std_[tid][2] = logf(gw / c_aw[besta]);
        std_[tid][3] = logf(gl / c_al[besta]);
        std_[tid][4] = tr[5];
        std_[tid][5] = tr[6];
        std_[tid][6] = tr[0];
        std_[tid][7] = gx - gw * 0.5f;
        std_[tid][8] = 1.6f * (gy - gl * 0.5f);
        std_[tid][9] = gx + gw * 0.5f;
        std_[tid][10] = 1.6f * (gy + gl * 0.5f);
    }

    // ---------------- per-cell derived values -------------------------------
    float sxv  = 1.0f / (1.0f + __expf(-c0));
    float syv  = 1.0f / (1.0f + __expf(-c1));
    float conf = 1.0f / (1.0f + __expf(-c6));

    float pw = __expf(c2) * c_aw[a];
    float pl = __expf(c3) * c_al[a];
    float px = sxv + (float)i;
    float py = syv + (float)j;

    float x1 = px - pw * 0.5f, x2 = px + pw * 0.5f;
    float y1s = 1.6f * (py - pl * 0.5f), y2s = 1.6f * (py + pl * 0.5f);
    float parea = pw * pl;
    float th = 0.6f * parea;

    // ---------------- exists(iou > 0.6) over culled targets -----------------
    const int nc = s_cnt;
    float bA = -1e30f, bB = -1e30f;
    int t = 0;
    for (; t + 2 <= nc; t += 2) {
        float4 q0 = cbox[t];
        float  n0 = cna[t];
        float4 q1 = cbox[t + 1];
        float  n1 = cna[t + 1];
        float cw0 = fminf(x2, q0.z) - fmaxf(x1, q0.x);
        float ch0 = fminf(y2s, q0.w) - fmaxf(y1s, q0.y);
        bA = fmaxf(bA, fmaf(fmaxf(cw0, 0.0f), ch0, n0));
        float cw1 = fminf(x2, q1.z) - fmaxf(x1, q1.x);
        float ch1 = fminf(y2s, q1.w) - fmaxf(y1s, q1.y);
        bB = fmaxf(bB, fmaf(fmaxf(cw1, 0.0f), ch1, n1));
    }
    if (t < nc) {
        float4 q0 = cbox[t];
        float  n0 = cna[t];
        float cw0 = fminf(x2, q0.z) - fmaxf(x1, q0.x);
        float ch0 = fminf(y2s, q0.w) - fmaxf(y1s, q0.y);
        bA = fmaxf(bA, fmaf(fmaxf(cw0, 0.0f), ch0, n0));
    }
    bool found = fmaxf(bA, bB) > th;

    __syncthreads();                                    // sync 3: std_ visible
    const int map = s_map[tid];
    float acc;
    if (map >= 0) {
        float dx   = sxv - std_[map][0];
        float dy   = syv - std_[map][1];
        float dw   = c2  - std_[map][2];
        float dl   = c3  - std_[map][3];
        float dim_ = c4  - std_[map][4];
        float dre  = c5  - std_[map][5];

        float bx1 = std_[map][7], by1s = std_[map][8];
        float bx2 = std_[map][9], by2s = std_[map][10];
        float cw  = fminf(x2, bx2) - fmaxf(x1, bx1);
        float chs = fminf(y2s, by2s) - fmaxf(y1s, by1s);
        float inter = fmaxf(cw, 0.0f) * fmaxf(chs, 0.0f) * 0.625f;
        float tgw = bx2 - bx1;
        float tgl = (by2s - by1s) * 0.625f;
        float uni = parea + tgw * tgl - inter;
        float tconf = inter / uni;
        float dconf = conf * 10.0f - tconf * 10.0f;

        // lazy class-logit loads (matched cells only)
        float cl[kC];
#pragma unroll
        for (int q = 0; q < kC; q++) cl[q] = base[(size_t)(7 + q) * kHW];
        float mx = cl[0];
#pragma unroll
        for (int q = 1; q < kC; q++) mx = fmaxf(mx, cl[q]);
        float s = 0.0f;
#pragma unroll
        for (int q = 0; q < kC; q++) s += __expf(cl[q] - mx);
        int tcls = (int)std_[map][6];
        float ce = mx + logf(s) - cl[tcls];

        acc = dx * dx + dy * dy + dw * dw + dl * dl + dim_ * dim_ + dre * dre
            + dconf * dconf + ce;
    } else {
        float cc = found ? 0.0f : conf;
        acc = cc * cc;
    }

    // ---------------- reduction (shuffle-based) ------------------------------
    float v = acc;
#pragma unroll
    for (int o = 16; o > 0; o >>= 1) v += __shfl_down_sync(0xffffffffu, v, o);
    if ((tid & 31) == 0) wred[tid >> 5] = v;
    __syncthreads();
    if (tid < 32) {
        float s = (tid < 8) ? wred[tid] : 0.0f;
#pragma unroll
        for (int o = 4; o > 0; o >>= 1) s += __shfl_down_sync(0xffffffffu, s, o);
        if (tid == 0) {
            g_partials[bid] = s;
            __threadfence();
            unsigned int r = atomicAdd(&g_count, 1u);
            s_last = (r == (unsigned)(kGrid - 1));
        }
    }
    __syncthreads();

    if (s_last) {
        float s = 0.0f;
        for (int p = tid; p < kGrid; p += 256) s += __ldcg(&g_partials[p]);
#pragma unroll
        for (int o = 16; o > 0; o >>= 1) s += __shfl_down_sync(0xffffffffu, s, o);
        if ((tid & 31) == 0) wred[tid >> 5] = s;
        __syncthreads();
        if (tid == 0) {
            float tot = 0.0f;
#pragma unroll
            for (int q = 0; q < 8; q++) tot += wred[q];
            loss[0] = tot;
            g_count = 0;
        }
        for (int p = 1 + tid; p < out_size; p += 256) loss[p] = 0.0f;
    }
}

extern "C" void kernel_launch(void* const* d_in, const int* in_sizes, int n_in,
                              void* d_out, int out_size) {
    const float* output = (const float*)d_in[0];
    const float* target = (const float*)d_in[1];
    k_fused<<<kGrid, 256>>>(output, target, (float*)d_out, out_size);
}

// round 9
// speedup vs baseline: 1.6970x; 1.0216x over previous
#include <cuda_runtime.h>

constexpr int kB = 32;
constexpr int kA = 5;
constexpr int kC = 8;
constexpr int kH = 32;
constexpr int kW = 64;
constexpr int kT = 50;
constexpr int kCh = 7 + kC;                 // 15
constexpr int kHW = kH * kW;                // 2048
constexpr int kCellsPerBlock = 512;         // 2 cells/thread: one anchor x 8 rows
constexpr int kBlocksPerB = 20;             // 10240 / 512
constexpr int kGrid = kB * kBlocksPerB;     // 640  -> single wave at 5 blocks/SM

__constant__ float c_aw[kA] = {1.08f, 3.42f, 6.63f, 9.42f, 16.62f};
__constant__ float c_al[kA] = {1.19f, 4.41f, 11.38f, 5.11f, 10.52f};

__device__ float        g_partials[kGrid];
__device__ unsigned int g_count = 0;   // self-resets -> graph-replay deterministic

__shared__ float4   cbox[kT];          // {x1, 1.6*y1, x2, 1.6*y2}
__shared__ float    cna[kT];           // -0.6 * target area
__shared__ float    std_[kT][12];      // tx,ty,tw,tl,tim,tre,tcls, x1,y1s,x2,y2s
__shared__ int      s_map[kCellsPerBlock];
__shared__ unsigned s_mask[2];
__shared__ int      s_cnt;
__shared__ float    wred[8];
__shared__ bool     s_last;

// matched-cell loss (rare: <=50 cells/batch). c4/c5/class logits loaded here.
__device__ __forceinline__ float matched_loss(
    int map, const float* __restrict__ base,
    float sxv, float syv, float conf, float c2, float c3,
    float x1, float x2, float y1s, float y2s, float parea)
{
    float c4 = base[4 * kHW];
    float c5 = base[5 * kHW];
    float dx   = sxv - std_[map][0];
    float dy   = syv - std_[map][1];
    float dw   = c2  - std_[map][2];
    float dl   = c3  - std_[map][3];
    float dim_ = c4  - std_[map][4];
    float dre  = c5  - std_[map][5];

    float bx1 = std_[map][7], by1s = std_[map][8];
    float bx2 = std_[map][9], by2s = std_[map][10];
    float cw  = fminf(x2, bx2) - fmaxf(x1, bx1);
    float chs = fminf(y2s, by2s) - fmaxf(y1s, by1s);
    float inter = fmaxf(cw, 0.0f) * fmaxf(chs, 0.0f) * 0.625f;
    float tgw = bx2 - bx1;
    float tgl = (by2s - by1s) * 0.625f;
    float uni = parea + tgw * tgl - inter;
    float tconf = inter / uni;
    float dconf = conf * 10.0f - tconf * 10.0f;

    float cl[kC];
#pragma unroll
    for (int q = 0; q < kC; q++) cl[q] = base[(size_t)(7 + q) * kHW];
    float mx = cl[0];
#pragma unroll
    for (int q = 1; q < kC; q++) mx = fmaxf(mx, cl[q]);
    float s = 0.0f;
#pragma unroll
    for (int q = 0; q < kC; q++) s += __expf(cl[q] - mx);
    int tcls = (int)std_[map][6];
    float ce = mx + logf(s) - cl[tcls];

    return dx * dx + dy * dy + dw * dw + dl * dl + dim_ * dim_ + dre * dre
         + dconf * dconf + ce;
}

__global__ void __launch_bounds__(256, 5) k_fused(const float* __restrict__ out,
                                                  const float* __restrict__ tgt,
                                                  float* __restrict__ loss,
                                                  int out_size) {
    const int tid = threadIdx.x;
    const int bid = blockIdx.x;
    const int b   = bid / kBlocksPerB;
    const int cb  = bid - b * kBlocksPerB;
    const int a   = cb >> 2;                       // anchor
    const int g8  = cb & 3;                        // 8-row group
    const int cellbase = cb * kCellsPerBlock;
    const int rem0 = (g8 << 9) + tid;              // within-anchor cell, rows jlo..jlo+3
    const int i   = rem0 & 63;
    const int j0  = rem0 >> 6;
    const int j1  = j0 + 4;                        // second cell: +256 -> +4 rows

    // hot-path channel LDGs first (c4/c5 are matched-path-only, loaded lazily)
    const float* base0 = out + ((size_t)(b * kA + a) * kCh) * kHW + rem0;
    const float* base1 = base0 + 256;
    float a0 = base0[0 * kHW];
    float a1 = base0[1 * kHW];
    float a2 = base0[2 * kHW];
    float a3 = base0[3 * kHW];
    float a6 = base0[6 * kHW];
    float b0 = base1[0 * kHW];
    float b1 = base1[1 * kHW];
    float b2 = base1[2 * kHW];
    float b3 = base1[3 * kHW];
    float b6 = base1[6 * kHW];

    // ---------------- phase 1: per-target values + masks --------------------
    s_map[tid] = -1;
    s_map[tid + 256] = -1;
    if (tid == 0) s_cnt = 0;

    const float* tr = tgt + ((size_t)b * kT + tid) * 7;
    bool validt = (tid < kT) && (tr[1] != 0.0f);
    unsigned bm = __ballot_sync(0xffffffffu, validt);
    if ((tid & 31) == 0 && tid < 64) s_mask[tid >> 5] = bm;

    float gx = 0.f, gy = 0.f, gw = 0.f, gl = 0.f, garea = 0.f;
    int gi = 0, gj = 0, besta = 0, off = -1;
    if (validt) {
        gx = tr[1] * (float)kW;
        gy = tr[2] * (float)kH;
        gw = tr[3] * (float)kW;
        gl = tr[4] * (float)kH;
        gi = min(max((int)gx, 0), kW - 1);
        gj = min(max((int)gy, 0), kH - 1);
        garea = gw * gl;

        // division-free first-max-wins anchor argmax
        float bin = fminf(gw, c_aw[0]) * fminf(gl, c_al[0]);
        float bun = garea + c_aw[0] * c_al[0] - bin;
#pragma unroll
        for (int q = 1; q < kA; q++) {
            float in_ = fminf(gw, c_aw[q]) * fminf(gl, c_al[q]);
            float un_ = garea + c_aw[q] * c_al[q] - in_;
            if (in_ * bun > bin * un_) { besta = q; bin = in_; bun = un_; }
        }
        off = ((besta * kH + gj) * kW + gi) - cellbase;
    }
    __syncthreads();                               // sync 1

    unsigned long long mm = (unsigned long long)s_mask[0]
                          | ((unsigned long long)s_mask[1] << 32);
    const int nv = __ffsll((long long)~mm) - 1;    // cumprod-validity prefix

    const bool inpfx = (tid < nv);
    if (inpfx) {
        if (off >= 0 && off < kCellsPerBlock) atomicMax(&s_map[off], tid);
        // y-cull over this block's 8 rows: IoU>0.6 needs |py-ty| < tl/3
        float tl3 = gl * (1.0f / 3.0f) + 1e-3f;
        float jlo = (float)(8 * g8);
        if (gy + tl3 > jlo && gy - tl3 < jlo + 8.0f) {
            int p = atomicAdd(&s_cnt, 1);
            cbox[p] = make_float4(gx - gw * 0.5f, 1.6f * (gy - gl * 0.5f),
                                  gx + gw * 0.5f, 1.6f * (gy + gl * 0.5f));
            cna[p]  = -0.6f * garea;
        }
    }
    __syncthreads();                               // sync 2

    // phase 2: dedupe winners write regression targets (hidden behind loop)
    if (inpfx && off >= 0 && off < kCellsPerBlock && s_map[off] == tid) {
        std_[tid][0] = gx - (float)gi;
        std_[tid][1] = gy - (float)gj;
        std_[tid][2] = logf(gw / c_aw[besta]);
        std_[tid][3] = logf(gl / c_al[besta]);
        std_[tid][4] = tr[5];
        std_[tid][5] = tr[6];
        std_[tid][6] = tr[0];
        std_[tid][7] = gx - gw * 0.5f;
        std_[tid][8] = 1.6f * (gy - gl * 0.5f);
        std_[tid][9] = gx + gw * 0.5f;
        std_[tid][10] = 1.6f * (gy + gl * 0.5f);
    }

    // ---------------- per-cell derived values -------------------------------
    float sxv0  = 1.0f / (1.0f + __expf(-a0));
    float syv0  = 1.0f / (1.0f + __expf(-a1));
    float conf0 = 1.0f / (1.0f + __expf(-a6));
    float sxv1  = 1.0f / (1.0f + __expf(-b0));
    float syv1  = 1.0f / (1.0f + __expf(-b1));
    float conf1 = 1.0f / (1.0f + __expf(-b6));

    float pw0 = __expf(a2) * c_aw[a];
    float pl0 = __expf(a3) * c_al[a];
    float pw1 = __expf(b2) * c_aw[a];
    float pl1 = __expf(b3) * c_al[a];

    float px0 = sxv0 + (float)i, py0 = syv0 + (float)j0;
    float px1 = sxv1 + (float)i, py1 = syv1 + (float)j1;

    float X1a = px0 - pw0 * 0.5f, X2a = px0 + pw0 * 0.5f;
    float Y1a = 1.6f * (py0 - pl0 * 0.5f), Y2a = 1.6f * (py0 + pl0 * 0.5f);
    float X1b = px1 - pw1 * 0.5f, X2b = px1 + pw1 * 0.5f;
    float Y1b = 1.6f * (py1 - pl1 * 0.5f), Y2b = 1.6f * (py1 + pl1 * 0.5f);

    float parea0 = pw0 * pl0, parea1 = pw1 * pl1;
    float th0 = 0.6f * parea0, th1 = 0.6f * parea1;

    // ---------------- exists(iou > 0.6): shared LDS across both cells -------
    const int nc = s_cnt;
    float m0A = -1e30f, m0B = -1e30f, m1A = -1e30f, m1B = -1e30f;
    int t = 0;
    for (; t + 2 <= nc; t += 2) {
        float4 q0 = cbox[t];
        float  n0 = cna[t];
        float4 q1 = cbox[t + 1];
        float  n1 = cna[t + 1];

        float cw0a = fminf(X2a, q0.z) - fmaxf(X1a, q0.x);
        float ch0a = fminf(Y2a, q0.w) - fmaxf(Y1a, q0.y);
        m0A = fmaxf(m0A, fmaf(fmaxf(cw0a, 0.0f), ch0a, n0));
        float cw0b = fminf(X2b, q0.z) - fmaxf(X1b, q0.x);
        float ch0b = fminf(Y2b, q0.w) - fmaxf(Y1b, q0.y);
        m1A = fmaxf(m1A, fmaf(fmaxf(cw0b, 0.0f), ch0b, n0));

        float cw1a = fminf(X2a, q1.z) - fmaxf(X1a, q1.x);
        float ch1a = fminf(Y2a, q1.w) - fmaxf(Y1a, q1.y);
        m0B = fmaxf(m0B, fmaf(fmaxf(cw1a, 0.0f), ch1a, n1));
        float cw1b = fminf(X2b, q1.z) - fmaxf(X1b, q1.x);
        float ch1b = fminf(Y2b, q1.w) - fmaxf(Y1b, q1.y);
        m1B = fmaxf(m1B, fmaf(fmaxf(cw1b, 0.0f), ch1b, n1));
    }
    if (t < nc) {
        float4 q0 = cbox[t];
        float  n0 = cna[t];
        float cw0a = fminf(X2a, q0.z) - fmaxf(X1a, q0.x);
        float ch0a = fminf(Y2a, q0.w) - fmaxf(Y1a, q0.y);
        m0A = fmaxf(m0A, fmaf(fmaxf(cw0a, 0.0f), ch0a, n0));
        float cw0b = fminf(X2b, q0.z) - fmaxf(X1b, q0.x);
        float ch0b = fminf(Y2b, q0.w) - fmaxf(Y1b, q0.y);
        m1A = fmaxf(m1A, fmaf(fmaxf(cw0b, 0.0f), ch0b, n0));
    }
    bool found0 = fmaxf(m0A, m0B) > th0;
    bool found1 = fmaxf(m1A, m1B) > th1;

    __syncthreads();                               // sync 3: std_ visible
    const int map0 = s_map[tid];
    const int map1 = s_map[tid + 256];

    float acc0, acc1;
    if (map0 >= 0) {
        acc0 = matched_loss(map0, base0, sxv0, syv0, conf0, a2, a3,
                            X1a, X2a, Y1a, Y2a, parea0);
    } else {
        float cc = found0 ? 0.0f : conf0;
        acc0 = cc * cc;
    }
    if (map1 >= 0) {
        acc1 = matched_loss(map1, base1, sxv1, syv1, conf1, b2, b3,
                            X1b, X2b, Y1b, Y2b, parea1);
    } else {
        float cc = found1 ? 0.0f : conf1;
        acc1 = cc * cc;
    }

    // ---------------- reduction (shuffle-based) -----------------------------
    float v = acc0 + acc1;
#pragma unroll
    for (int o = 16; o > 0; o >>= 1) v += __shfl_down_sync(0xffffffffu, v, o);
    if ((tid & 31) == 0) wred[tid >> 5] = v;
    __syncthreads();
    if (tid < 32) {
        float s = (tid < 8) ? wred[tid] : 0.0f;
#pragma unroll
        for (int o = 4; o > 0; o >>= 1) s += __shfl_down_sync(0xffffffffu, s, o);
        if (tid == 0) {
            g_partials[bid] = s;
            __threadfence();
            unsigned int r = atomicAdd(&g_count, 1u);
            s_last = (r == (unsigned)(kGrid - 1));
        }
    }
    __syncthreads();

    if (s_last) {
        float s = 0.0f;
        for (int p = tid; p < kGrid; p += 256) s += __ldcg(&g_partials[p]);
#pragma unroll
        for (int o = 16; o > 0; o >>= 1) s += __shfl_down_sync(0xffffffffu, s, o);
        if ((tid & 31) == 0) wred[tid >> 5] = s;
        __syncthreads();
        if (tid == 0) {
            float tot = 0.0f;
#pragma unroll
            for (int q = 0; q < 8; q++) tot += wred[q];
            loss[0] = tot;
            g_count = 0;
        }
        for (int p = 1 + tid; p < out_size; p += 256) loss[p] = 0.0f;
    }
}

extern "C" void kernel_launch(void* const* d_in, const int* in_sizes, int n_in,
                              void* d_out, int out_size) {
    const float* output = (const float*)d_in[0];
    const float* target = (const float*)d_in[1];
    k_fused<<<kGrid, 256>>>(output, target, (float*)d_out, out_size);
}

// round 10
// speedup vs baseline: 1.9600x; 1.1550x over previous
#include <cuda_runtime.h>

constexpr int kB = 32;
constexpr int kA = 5;
constexpr int kC = 8;
constexpr int kH = 32;
constexpr int kW = 64;
constexpr int kT = 50;
constexpr int kCh = 7 + kC;                 // 15
constexpr int kHW = kH * kW;                // 2048
constexpr int kCellsPerBlock = 512;         // 2 cells/thread: one anchor x 8 rows
constexpr int kBlocksPerB = 20;             // 10240 / 512
constexpr int kGrid = kB * kBlocksPerB;     // 640

__constant__ float c_aw[kA] = {1.08f, 3.42f, 6.63f, 9.42f, 16.62f};
__constant__ float c_al[kA] = {1.19f, 4.41f, 11.38f, 5.11f, 10.52f};

__device__ float        g_partials[kGrid];
__device__ unsigned int g_count = 0;   // self-resets -> graph-replay deterministic

__shared__ float4   cbox[kT];          // {x1, 1.6*y1, x2, 1.6*y2}
__shared__ float    cna[kT];           // -0.6 * target area
__shared__ float2   sxw[kT];           // {txc - tw/3 - eps, txc + tw/3 + eps}
__shared__ float2   syw[kT];           // {tyc - tl/3 - eps, tyc + tl/3 + eps}
__shared__ float    std_[kT][12];      // tx,ty,tw,tl,tim,tre,tcls, x1,y1s,x2,y2s
__shared__ int      s_map[kCellsPerBlock];
__shared__ unsigned s_mask[2];
__shared__ int      s_cnt;
__shared__ float    wred[8];
__shared__ bool     s_last;

// matched-cell loss (rare: <=50 cells/batch)
__device__ __forceinline__ float matched_loss(
    int map, const float* __restrict__ base,
    float sxv, float syv, float conf, float c2, float c3,
    float x1, float x2, float y1s, float y2s, float parea)
{
    float c4 = base[4 * kHW];
    float c5 = base[5 * kHW];
    float dx   = sxv - std_[map][0];
    float dy   = syv - std_[map][1];
    float dw   = c2  - std_[map][2];
    float dl   = c3  - std_[map][3];
    float dim_ = c4  - std_[map][4];
    float dre  = c5  - std_[map][5];

    float bx1 = std_[map][7], by1s = std_[map][8];
    float bx2 = std_[map][9], by2s = std_[map][10];
    float cw  = fminf(x2, bx2) - fmaxf(x1, bx1);
    float chs = fminf(y2s, by2s) - fmaxf(y1s, by1s);
    float inter = fmaxf(cw, 0.0f) * fmaxf(chs, 0.0f) * 0.625f;
    float tgw = bx2 - bx1;
    float tgl = (by2s - by1s) * 0.625f;
    float uni = parea + tgw * tgl - inter;
    float tconf = inter / uni;
    float dconf = conf * 10.0f - tconf * 10.0f;

    float cl[kC];
#pragma unroll
    for (int q = 0; q < kC; q++) cl[q] = base[(size_t)(7 + q) * kHW];
    float mx = cl[0];
#pragma unroll
    for (int q = 1; q < kC; q++) mx = fmaxf(mx, cl[q]);
    float s = 0.0f;
#pragma unroll
    for (int q = 0; q < kC; q++) s += __expf(cl[q] - mx);
    int tcls = (int)std_[map][6];
    float ce = mx + logf(s) - cl[tcls];

    return dx * dx + dy * dy + dw * dw + dl * dl + dim_ * dim_ + dre * dre
         + dconf * dconf + ce;
}

__global__ void __launch_bounds__(256, 5) k_fused(const float* __restrict__ out,
                                                  const float* __restrict__ tgt,
                                                  float* __restrict__ loss,
                                                  int out_size) {
    const int tid = threadIdx.x;
    const int bid = blockIdx.x;
    const int b   = bid / kBlocksPerB;
    const int cb  = bid - b * kBlocksPerB;
    const int a   = cb >> 2;                       // anchor
    const int g8  = cb & 3;                        // 8-row group
    const int cellbase = cb * kCellsPerBlock;

    // warp tiling: 16 cols x 2 rows per slot; slot1 = +4 rows
    const int lane = tid & 31;
    const int wrp  = tid >> 5;
    const int xT   = wrp & 3;
    const int yT   = wrp >> 2;
    const int i    = (xT << 4) + (lane & 15);
    const int rowLocal0 = (yT << 1) + (lane >> 4); // 0..7
    const int j0   = (g8 << 3) + rowLocal0;
    const int j1   = j0 + 4;
    const int off0 = (rowLocal0 << 6) + i;         // s_map index, slot0
    const int rem0 = (j0 << 6) + i;                // within-anchor cell

    // hot-path channel LDGs first (c4/c5 matched-path-only)
    const float* base0 = out + ((size_t)(b * kA + a) * kCh) * kHW + rem0;
    const float* base1 = base0 + 256;              // +4 rows
    float a0 = base0[0 * kHW];
    float a1 = base0[1 * kHW];
    float a2 = base0[2 * kHW];
    float a3 = base0[3 * kHW];
    float a6 = base0[6 * kHW];
    float b0 = base1[0 * kHW];
    float b1 = base1[1 * kHW];
    float b2 = base1[2 * kHW];
    float b3 = base1[3 * kHW];
    float b6 = base1[6 * kHW];

    // ---------------- phase 1: per-target values + masks --------------------
    s_map[tid] = -1;
    s_map[tid + 256] = -1;
    if (tid == 0) s_cnt = 0;

    const float* tr = tgt + ((size_t)b * kT + tid) * 7;
    bool validt = (tid < kT) && (tr[1] != 0.0f);
    unsigned bm = __ballot_sync(0xffffffffu, validt);
    if ((tid & 31) == 0 && tid < 64) s_mask[tid >> 5] = bm;

    float gx = 0.f, gy = 0.f, gw = 0.f, gl = 0.f, garea = 0.f;
    int gi = 0, gj = 0, besta = 0, off = -1;
    if (validt) {
        gx = tr[1] * (float)kW;
        gy = tr[2] * (float)kH;
        gw = tr[3] * (float)kW;
        gl = tr[4] * (float)kH;
        gi = min(max((int)gx, 0), kW - 1);
        gj = min(max((int)gy, 0), kH - 1);
        garea = gw * gl;

        // division-free first-max-wins anchor argmax
        float bin = fminf(gw, c_aw[0]) * fminf(gl, c_al[0]);
        float bun = garea + c_aw[0] * c_al[0] - bin;
#pragma unroll
        for (int q = 1; q < kA; q++) {
            float in_ = fminf(gw, c_aw[q]) * fminf(gl, c_al[q]);
            float un_ = garea + c_aw[q] * c_al[q] - in_;
            if (in_ * bun > bin * un_) { besta = q; bin = in_; bun = un_; }
        }
        off = ((besta * kH + gj) * kW + gi) - cellbase;
    }
    __syncthreads();                               // sync 1

    unsigned long long mm = (unsigned long long)s_mask[0]
                          | ((unsigned long long)s_mask[1] << 32);
    const int nv = __ffsll((long long)~mm) - 1;    // cumprod-validity prefix

    const bool inpfx = (tid < nv);
    if (inpfx) {
        if (off >= 0 && off < kCellsPerBlock) atomicMax(&s_map[off], tid);
        // block-level y-cull over 8 rows: IoU>0.6 needs |pyc-tyc| < tl/3
        float tl3 = gl * (1.0f / 3.0f) + 1e-3f;
        float jlo = (float)(8 * g8);
        if (gy + tl3 > jlo && gy - tl3 < jlo + 8.0f) {
            int p = atomicAdd(&s_cnt, 1);
            cbox[p] = make_float4(gx - gw * 0.5f, 1.6f * (gy - gl * 0.5f),
                                  gx + gw * 0.5f, 1.6f * (gy + gl * 0.5f));
            cna[p]  = -0.6f * garea;
            float tw3 = gw * (1.0f / 3.0f) + 1e-3f;
            sxw[p] = make_float2(gx - tw3, gx + tw3);
            syw[p] = make_float2(gy - tl3, gy + tl3);
        }
    }
    __syncthreads();                               // sync 2

    // phase 2: dedupe winners write regression targets (hidden behind loop)
    if (inpfx && off >= 0 && off < kCellsPerBlock && s_map[off] == tid) {
        std_[tid][0] = gx - (float)gi;
        std_[tid][1] = gy - (float)gj;
        std_[tid][2] = logf(gw / c_aw[besta]);
        std_[tid][3] = logf(gl / c_al[besta]);
        std_[tid][4] = tr[5];
        std_[tid][5] = tr[6];
        std_[tid][6] = tr[0];
        std_[tid][7] = gx - gw * 0.5f;
        std_[tid][8] = 1.6f * (gy - gl * 0.5f);
        std_[tid][9] = gx + gw * 0.5f;
        std_[tid][10] = 1.6f * (gy + gl * 0.5f);
    }

    // ---------------- per-cell derived values -------------------------------
    float sxv0  = 1.0f / (1.0f + __expf(-a0));
    float syv0  = 1.0f / (1.0f + __expf(-a1));
    float conf0 = 1.0f / (1.0f + __expf(-a6));
    float sxv1  = 1.0f / (1.0f + __expf(-b0));
    float syv1  = 1.0f / (1.0f + __expf(-b1));
    float conf1 = 1.0f / (1.0f + __expf(-b6));

    float pw0 = __expf(a2) * c_aw[a];
    float pl0 = __expf(a3) * c_al[a];
    float pw1 = __expf(b2) * c_aw[a];
    float pl1 = __expf(b3) * c_al[a];

    float px0 = sxv0 + (float)i, py0 = syv0 + (float)j0;
    float px1 = sxv1 + (float)i, py1 = syv1 + (float)j1;

    float X1a = px0 - pw0 * 0.5f, X2a = px0 + pw0 * 0.5f;
    float Y1a = 1.6f * (py0 - pl0 * 0.5f), Y2a = 1.6f * (py0 + pl0 * 0.5f);
    float X1b = px1 - pw1 * 0.5f, X2b = px1 + pw1 * 0.5f;
    float Y1b = 1.6f * (py1 - pl1 * 0.5f), Y2b = 1.6f * (py1 + pl1 * 0.5f);

    float parea0 = pw0 * pl0, parea1 = pw1 * pl1;
    float th0 = 0.6f * parea0, th1 = 0.6f * parea1;

    // ---------------- per-warp x/y culling bitmask --------------------------
    // Warp spans cols [16xT, 16xT+16), rows {2yT, 2yT+1, 2yT+4, 2yT+5} (+g8 base).
    // pxc in (colLo, colLo+16); pyc in (rowLo, rowLo+6).
    const int nc = s_cnt;
    const float colLo = (float)(xT << 4);
    const float rowLo = (float)((g8 << 3) + (yT << 1));
    unsigned mk0, mk1;
    {
        bool p0 = false, p1 = false;
        if (lane < nc) {
            float2 xw = sxw[lane];
            float2 yw = syw[lane];
            p0 = (xw.y > colLo) && (xw.x < colLo + 16.0f)
              && (yw.y > rowLo) && (yw.x < rowLo + 6.0f);
        }
        int l2 = lane + 32;
        if (l2 < nc) {
            float2 xw = sxw[l2];
            float2 yw = syw[l2];
            p1 = (xw.y > colLo) && (xw.x < colLo + 16.0f)
              && (yw.y > rowLo) && (yw.x < rowLo + 6.0f);
        }
        mk0 = __ballot_sync(0xffffffffu, p0);
        mk1 = __ballot_sync(0xffffffffu, p1);
    }

    // ---------------- exists(iou > 0.6) over bitmask survivors --------------
    float m0 = -1e30f, m1 = -1e30f;
    unsigned m = mk0;
    int basebit = 0;
#pragma unroll 2
    for (int half = 0; half < 2; half++) {
        while (m) {
            int t = basebit + __ffs(m) - 1;
            m &= m - 1;
            float4 q = cbox[t];
            float  n = cna[t];
            float cw0 = fminf(X2a, q.z) - fmaxf(X1a, q.x);
            float ch0 = fminf(Y2a, q.w) - fmaxf(Y1a, q.y);
            m0 = fmaxf(m0, fmaf(fmaxf(cw0, 0.0f), ch0, n));
            float cw1 = fminf(X2b, q.z) - fmaxf(X1b, q.x);
            float ch1 = fminf(Y2b, q.w) - fmaxf(Y1b, q.y);
            m1 = fmaxf(m1, fmaf(fmaxf(cw1, 0.0f), ch1, n));
        }
        m = mk1;
        basebit = 32;
    }
    bool found0 = m0 > th0;
    bool found1 = m1 > th1;

    __syncthreads();                               // sync 3: std_ visible
    const int map0 = s_map[off0];
    const int map1 = s_map[off0 + 256];

    float acc0, acc1;
    if (map0 >= 0) {
        acc0 = matched_loss(map0, base0, sxv0, syv0, conf0, a2, a3,
                            X1a, X2a, Y1a, Y2a, parea0);
    } else {
        float cc = found0 ? 0.0f : conf0;
        acc0 = cc * cc;
    }
    if (map1 >= 0) {
        acc1 = matched_loss(map1, base1, sxv1, syv1, conf1, b2, b3,
                            X1b, X2b, Y1b, Y2b, parea1);
    } else {
        float cc = found1 ? 0.0f : conf1;
        acc1 = cc * cc;
    }

    // ---------------- reduction (shuffle-based) -----------------------------
    float v = acc0 + acc1;
#pragma unroll
    for (int o = 16; o > 0; o >>= 1) v += __shfl_down_sync(0xffffffffu, v, o);
    if (lane == 0) wred[wrp] = v;
    __syncthreads();
    if (tid < 32) {
        float s = (tid < 8) ? wred[tid] : 0.0f;
#pragma unroll
        for (int o = 4; o > 0; o >>= 1) s += __shfl_down_sync(0xffffffffu, s, o);
        if (tid == 0) {
            g_partials[bid] = s;
            __threadfence();
            unsigned int r = atomicAdd(&g_count, 1u);
            s_last = (r == (unsigned)(kGrid - 1));
        }
    }
    __syncthreads();

    if (s_last) {
        float s = 0.0f;
        for (int p = tid; p < kGrid; p += 256) s += __ldcg(&g_partials[p]);
#pragma unroll
        for (int o = 16; o > 0; o >>= 1) s += __shfl_down_sync(0xffffffffu, s, o);
        if (lane == 0) wred[wrp] = s;
        __syncthreads();
        if (tid == 0) {
            float tot = 0.0f;
#pragma unroll
            for (int q = 0; q < 8; q++) tot += wred[q];
            loss[0] = tot;
            g_count = 0;
        }
        for (int p = 1 + tid; p < out_size; p += 256) loss[p] = 0.0f;
    }
}

extern "C" void kernel_launch(void* const* d_in, const int* in_sizes, int n_in,
                              void* d_out, int out_size) {
    const float* output = (const float*)d_in[0];
    const float* target = (const float*)d_in[1];
    k_fused<<<kGrid, 256>>>(output, target, (float*)d_out, out_size);
}

// round 11
// speedup vs baseline: 1.9649x; 1.0025x over previous
#include <cuda_runtime.h>

constexpr int kB = 32;
constexpr int kA = 5;
constexpr int kC = 8;
constexpr int kH = 32;
constexpr int kW = 64;
constexpr int kT = 50;
constexpr int kCh = 7 + kC;                 // 15
constexpr int kHW = kH * kW;                // 2048
constexpr int kCellsPerBlock = 512;         // 2 cells/thread (x-pairs): one anchor x 8 rows
constexpr int kBlocksPerB = 20;             // 10240 / 512
constexpr int kGrid = kB * kBlocksPerB;     // 640

__constant__ float c_aw[kA] = {1.08f, 3.42f, 6.63f, 9.42f, 16.62f};
__constant__ float c_al[kA] = {1.19f, 4.41f, 11.38f, 5.11f, 10.52f};

__device__ float        g_partials[kGrid];
__device__ unsigned int g_count = 0;   // self-resets -> graph-replay deterministic

__shared__ float4   cbox[kT];          // {x1, 1.6*y1, x2, 1.6*y2}
__shared__ float    cna[kT];           // -0.6 * target area
__shared__ float2   sxw[kT];           // x-window {txc - tw/3 - eps, txc + tw/3 + eps}
__shared__ float2   syw[kT];           // y-window {tyc - tl/3 - eps, tyc + tl/3 + eps}
__shared__ float    std_[kT][12];      // tx,ty,tw,tl,tim,tre,tcls, x1,y1s,x2,y2s
__shared__ int      s_map[kCellsPerBlock];
__shared__ unsigned s_mask[2];
__shared__ int      s_cnt;
__shared__ float    wred[8];
__shared__ bool     s_last;

// matched-cell loss (rare: <=50 cells/batch)
__device__ __forceinline__ float matched_loss(
    int map, const float* __restrict__ base,
    float sxv, float syv, float conf, float c2, float c3,
    float x1, float x2, float y1s, float y2s, float parea)
{
    float c4 = base[4 * kHW];
    float c5 = base[5 * kHW];
    float dx   = sxv - std_[map][0];
    float dy   = syv - std_[map][1];
    float dw   = c2  - std_[map][2];
    float dl   = c3  - std_[map][3];
    float dim_ = c4  - std_[map][4];
    float dre  = c5  - std_[map][5];

    float bx1 = std_[map][7], by1s = std_[map][8];
    float bx2 = std_[map][9], by2s = std_[map][10];
    float cw  = fminf(x2, bx2) - fmaxf(x1, bx1);
    float chs = fminf(y2s, by2s) - fmaxf(y1s, by1s);
    float inter = fmaxf(cw, 0.0f) * fmaxf(chs, 0.0f) * 0.625f;
    float tgw = bx2 - bx1;
    float tgl = (by2s - by1s) * 0.625f;
    float uni = parea + tgw * tgl - inter;
    float tconf = inter / uni;
    float dconf = conf * 10.0f - tconf * 10.0f;

    float cl[kC];
#pragma unroll
    for (int q = 0; q < kC; q++) cl[q] = base[(size_t)(7 + q) * kHW];
    float mx = cl[0];
#pragma unroll
    for (int q = 1; q < kC; q++) mx = fmaxf(mx, cl[q]);
    float s = 0.0f;
#pragma unroll
    for (int q = 0; q < kC; q++) s += __expf(cl[q] - mx);
    int tcls = (int)std_[map][6];
    float ce = mx + logf(s) - cl[tcls];

    return dx * dx + dy * dy + dw * dw + dl * dl + dim_ * dim_ + dre * dre
         + dconf * dconf + ce;
}

__global__ void __launch_bounds__(256, 6) k_fused(const float* __restrict__ out,
                                                  const float* __restrict__ tgt,
                                                  float* __restrict__ loss,
                                                  int out_size) {
    const int tid = threadIdx.x;
    const int bid = blockIdx.x;
    const int b   = bid / kBlocksPerB;
    const int cb  = bid - b * kBlocksPerB;
    const int a   = cb >> 2;                       // anchor
    const int g8  = cb & 3;                        // 8-row group
    const int cellbase = cb * kCellsPerBlock;

    // warp tiling: 16 cols x 4 contiguous rows; thread = x-pair (i, i+1)
    const int lane = tid & 31;
    const int wrp  = tid >> 5;
    const int xT   = wrp & 3;
    const int yT   = wrp >> 2;                     // 0..1
    const int i0   = (xT << 4) + ((lane & 7) << 1);
    const int rowLocal = (yT << 2) + (lane >> 3);  // 0..7
    const int j    = (g8 << 3) + rowLocal;
    const int off0 = (rowLocal << 6) + i0;         // s_map index (slot1 = +1)
    const int rem0 = (j << 6) + i0;                // even -> float2-aligned

    // hot channels as float2 (cells i0, i0+1); c4/c5 matched-path-only
    const float* base0 = out + ((size_t)(b * kA + a) * kCh) * kHW + rem0;
    float2 v0 = *reinterpret_cast<const float2*>(base0 + 0 * kHW);
    float2 v1 = *reinterpret_cast<const float2*>(base0 + 1 * kHW);
    float2 v2 = *reinterpret_cast<const float2*>(base0 + 2 * kHW);
    float2 v3 = *reinterpret_cast<const float2*>(base0 + 3 * kHW);
    float2 v6 = *reinterpret_cast<const float2*>(base0 + 6 * kHW);

    // ---------------- phase 1: per-target values + masks --------------------
    s_map[tid] = -1;
    s_map[tid + 256] = -1;
    if (tid == 0) s_cnt = 0;

    const float* tr = tgt + ((size_t)b * kT + tid) * 7;
    bool validt = (tid < kT) && (tr[1] != 0.0f);
    unsigned bm = __ballot_sync(0xffffffffu, validt);
    if ((tid & 31) == 0 && tid < 64) s_mask[tid >> 5] = bm;

    float gx = 0.f, gy = 0.f, gw = 0.f, gl = 0.f, garea = 0.f;
    int gi = 0, gj = 0, besta = 0, off = -1;
    if (validt) {
        gx = tr[1] * (float)kW;
        gy = tr[2] * (float)kH;
        gw = tr[3] * (float)kW;
        gl = tr[4] * (float)kH;
        gi = min(max((int)gx, 0), kW - 1);
        gj = min(max((int)gy, 0), kH - 1);
        garea = gw * gl;

        // division-free first-max-wins anchor argmax
        float bin = fminf(gw, c_aw[0]) * fminf(gl, c_al[0]);
        float bun = garea + c_aw[0] * c_al[0] - bin;
#pragma unroll
        for (int q = 1; q < kA; q++) {
            float in_ = fminf(gw, c_aw[q]) * fminf(gl, c_al[q]);
            float un_ = garea + c_aw[q] * c_al[q] - in_;
            if (in_ * bun > bin * un_) { besta = q; bin = in_; bun = un_; }
        }
        off = ((besta * kH + gj) * kW + gi) - cellbase;
    }
    __syncthreads();                               // sync 1

    unsigned long long mm = (unsigned long long)s_mask[0]
                          | ((unsigned long long)s_mask[1] << 32);
    const int nv = __ffsll((long long)~mm) - 1;    // cumprod-validity prefix

    const bool inpfx = (tid < nv);
    if (inpfx) {
        if (off >= 0 && off < kCellsPerBlock) atomicMax(&s_map[off], tid);
        // block-level y-cull over 8 rows: IoU>0.6 needs |pyc-tyc| < tl/3
        float tl3 = gl * (1.0f / 3.0f) + 1e-3f;
        float jlo = (float)(8 * g8);
        if (gy + tl3 > jlo && gy - tl3 < jlo + 8.0f) {
            int p = atomicAdd(&s_cnt, 1);
            cbox[p] = make_float4(gx - gw * 0.5f, 1.6f * (gy - gl * 0.5f),
                                  gx + gw * 0.5f, 1.6f * (gy + gl * 0.5f));
            cna[p]  = -0.6f * garea;
            float tw3 = gw * (1.0f / 3.0f) + 1e-3f;
            sxw[p] = make_float2(gx - tw3, gx + tw3);
            syw[p] = make_float2(gy - tl3, gy + tl3);
        }
    }
    __syncthreads();                               // sync 2

    // phase 2: dedupe winners write regression targets (hidden behind loop)
    if (inpfx && off >= 0 && off < kCellsPerBlock && s_map[off] == tid) {
        std_[tid][0] = gx - (float)gi;
        std_[tid][1] = gy - (float)gj;
        std_[tid][2] = logf(gw / c_aw[besta]);
        std_[tid][3] = logf(gl / c_al[besta]);
        std_[tid][4] = tr[5];
        std_[tid][5] = tr[6];
        std_[tid][6] = tr[0];
        std_[tid][7] = gx - gw * 0.5f;
        std_[tid][8] = 1.6f * (gy - gl * 0.5f);
        std_[tid][9] = gx + gw * 0.5f;
        std_[tid][10] = 1.6f * (gy + gl * 0.5f);
    }

    // ---------------- per-cell derived values -------------------------------
    float sxv0  = 1.0f / (1.0f + __expf(-v0.x));
    float syv0  = 1.0f / (1.0f + __expf(-v1.x));
    float conf0 = 1.0f / (1.0f + __expf(-v6.x));
    float sxv1  = 1.0f / (1.0f + __expf(-v0.y));
    float syv1  = 1.0f / (1.0f + __expf(-v1.y));
    float conf1 = 1.0f / (1.0f + __expf(-v6.y));

    float pw0 = __expf(v2.x) * c_aw[a];
    float pl0 = __expf(v3.x) * c_al[a];
    float pw1 = __expf(v2.y) * c_aw[a];
    float pl1 = __expf(v3.y) * c_al[a];

    float px0 = sxv0 + (float)i0,       py0 = syv0 + (float)j;
    float px1 = sxv1 + (float)(i0 + 1), py1 = syv1 + (float)j;

    float X1a = px0 - pw0 * 0.5f, X2a = px0 + pw0 * 0.5f;
    float Y1a = 1.6f * (py0 - pl0 * 0.5f), Y2a = 1.6f * (py0 + pl0 * 0.5f);
    float X1b = px1 - pw1 * 0.5f, X2b = px1 + pw1 * 0.5f;
    float Y1b = 1.6f * (py1 - pl1 * 0.5f), Y2b = 1.6f * (py1 + pl1 * 0.5f);

    float parea0 = pw0 * pl0, parea1 = pw1 * pl1;
    float th0 = 0.6f * parea0, th1 = 0.6f * parea1;

    // ---------------- per-warp x/y culling bitmask --------------------------
    // Warp spans cols [16xT, 16xT+16), rows [rowLo, rowLo+4).
    const int nc = s_cnt;
    const float colLo = (float)(xT << 4);
    const float rowLo = (float)((g8 << 3) + (yT << 2));
    unsigned mk0, mk1;
    {
        bool p0 = false, p1 = false;
        if (lane < nc) {
            float2 xw = sxw[lane];
            float2 yw = syw[lane];
            p0 = (xw.y > colLo) && (xw.x < colLo + 16.0f)
              && (yw.y > rowLo) && (yw.x < rowLo + 4.0f);
        }
        int l2 = lane + 32;
        if (l2 < nc) {
            float2 xw = sxw[l2];
            float2 yw = syw[l2];
            p1 = (xw.y > colLo) && (xw.x < colLo + 16.0f)
              && (yw.y > rowLo) && (yw.x < rowLo + 4.0f);
        }
        mk0 = __ballot_sync(0xffffffffu, p0);
        mk1 = __ballot_sync(0xffffffffu, p1);
    }

    // ---------------- exists(iou > 0.6) over bitmask survivors --------------
    float m0 = -1e30f, m1 = -1e30f;
    unsigned m = mk0;
    int basebit = 0;
#pragma unroll 2
    for (int half = 0; half < 2; half++) {
        while (m) {
            int t = basebit + __ffs(m) - 1;
            m &= m - 1;
            float4 q = cbox[t];
            float  n = cna[t];
            float cw0 = fminf(X2a, q.z) - fmaxf(X1a, q.x);
            float ch0 = fminf(Y2a, q.w) - fmaxf(Y1a, q.y);
            m0 = fmaxf(m0, fmaf(fmaxf(cw0, 0.0f), ch0, n));
            float cw1 = fminf(X2b, q.z) - fmaxf(X1b, q.x);
            float ch1 = fminf(Y2b, q.w) - fmaxf(Y1b, q.y);
            m1 = fmaxf(m1, fmaf(fmaxf(cw1, 0.0f), ch1, n));
        }
        m = mk1;
        basebit = 32;
    }
    bool found0 = m0 > th0;
    bool found1 = m1 > th1;

    __syncthreads();                               // sync 3: std_ visible
    const int map0 = s_map[off0];
    const int map1 = s_map[off0 + 1];

    float acc0, acc1;
    if (map0 >= 0) {
        acc0 = matched_loss(map0, base0, sxv0, syv0, conf0, v2.x, v3.x,
                            X1a, X2a, Y1a, Y2a, parea0);
    } else {
        float cc = found0 ? 0.0f : conf0;
        acc0 = cc * cc;
    }
    if (map1 >= 0) {
        acc1 = matched_loss(map1, base0 + 1, sxv1, syv1, conf1, v2.y, v3.y,
                            X1b, X2b, Y1b, Y2b, parea1);
    } else {
        float cc = found1 ? 0.0f : conf1;
        acc1 = cc * cc;
    }

    // ---------------- reduction (shuffle-based) -----------------------------
    float v = acc0 + acc1;
#pragma unroll
    for (int o = 16; o > 0; o >>= 1) v += __shfl_down_sync(0xffffffffu, v, o);
    if (lane == 0) wred[wrp] = v;
    __syncthreads();
    if (tid < 32) {
        float s = (tid < 8) ? wred[tid] : 0.0f;
#pragma unroll
        for (int o = 4; o > 0; o >>= 1) s += __shfl_down_sync(0xffffffffu, s, o);
        if (tid == 0) {
            g_partials[bid] = s;
            __threadfence();
            unsigned int r = atomicAdd(&g_count, 1u);
            s_last = (r == (unsigned)(kGrid - 1));
        }
    }
    __syncthreads();

    if (s_last) {
        float s = 0.0f;
        for (int p = tid; p < kGrid; p += 256) s += __ldcg(&g_partials[p]);
#pragma unroll
        for (int o = 16; o > 0; o >>= 1) s += __shfl_down_sync(0xffffffffu, s, o);
        if (lane == 0) wred[wrp] = s;
        __syncthreads();
        if (tid == 0) {
            float tot = 0.0f;
#pragma unroll
            for (int q = 0; q < 8; q++) tot += wred[q];
            loss[0] = tot;
            g_count = 0;
        }
        for (int p = 1 + tid; p < out_size; p += 256) loss[p] = 0.0f;
    }
}

extern "C" void kernel_launch(void* const* d_in, const int* in_sizes, int n_in,
                              void* d_out, int out_size) {
    const float* output = (const float*)d_in[0];
    const float* target = (const float*)d_in[1];
    k_fused<<<kGrid, 256>>>(output, target, (float*)d_out, out_size);
}